// round 13
// baseline (speedup 1.0000x reference)
#include <cuda_runtime.h>
#include <cuda_fp16.h>
#include <cstdint>

// CosinePrediction: cos[e] = <u[src[e]], v[dst[e]]> / (||u||*||v||)
// Phase 1 (single fused launch): L2-normalize ALL rows of both tensors,
//   store fp16 rows (128 B/row) in scratch. 4 rows per thread -> 8
//   independent float4 loads in flight (R6 profile showed latency-limited).
// Phase 2: PERSISTENT gather, exact R8 shape (measured optimum across
//   R9/R10/R11 probes): 8 lanes per edge-quad, uint4 loads, index prefetch
//   one iteration ahead, depth-2 fp16 dot accumulation, 4 blocks/SM.

static constexpr int D = 64;
static constexpr int MAX_ROWS = 100000;       // N_U = N_I = 100000 (fixed problem shape)
static constexpr int THREADS = 256;
static constexpr int GATHER_BLOCKS = 592;     // 4 blocks/SM * 148 SMs, persistent

// fp16 normalized rows (25.6 MB total scratch)
__device__ __half g_nu[(size_t)MAX_ROWS * D];
__device__ __half g_ni[(size_t)MAX_ROWS * D];

// ---------------- Phase 1: fused normalize + fp16 convert ----------------
__device__ __forceinline__ void norm_store(
    const float4 a, const float4 b, float rn, __half* __restrict__ drow, int lane)
{
    __half2 h[4];
    h[0] = __floats2half2_rn(a.x * rn, a.y * rn);
    h[1] = __floats2half2_rn(a.z * rn, a.w * rn);
    h[2] = __floats2half2_rn(b.x * rn, b.y * rn);
    h[3] = __floats2half2_rn(b.z * rn, b.w * rn);
    *reinterpret_cast<uint2*>(drow + 4 * lane)      = *reinterpret_cast<uint2*>(&h[0]);
    *reinterpret_cast<uint2*>(drow + 32 + 4 * lane) = *reinterpret_cast<uint2*>(&h[2]);
}

__device__ __forceinline__ float sq8(const float4 a, const float4 b)
{
    float n = a.x * a.x;
    n = fmaf(a.y, a.y, n); n = fmaf(a.z, a.z, n); n = fmaf(a.w, a.w, n);
    n = fmaf(b.x, b.x, n); n = fmaf(b.y, b.y, n);
    n = fmaf(b.z, b.z, n); n = fmaf(b.w, b.w, n);
    return n;
}

__global__ __launch_bounds__(THREADS) void normalize_fused_kernel(
    const float* __restrict__ h_user,
    const float* __restrict__ h_item,
    int n_user, int n_total)
{
    const int gid  = blockIdx.x * THREADS + threadIdx.x;
    const int q    = gid >> 3;           // row-quad index
    const int lane = gid & 7;
    const int r0   = q * 4;
    if (r0 >= n_total) return;

    const float* src[4];
    __half*      dst[4];
    bool         live[4];
    #pragma unroll
    for (int j = 0; j < 4; j++) {
        const int r = r0 + j;
        live[j] = r < n_total;
        const int rc = live[j] ? r : r0;
        if (rc < n_user) {
            src[j] = h_user + (long long)rc * D;
            dst[j] = g_nu  + (long long)rc * D;
        } else {
            src[j] = h_item + (long long)(rc - n_user) * D;
            dst[j] = g_ni  + (long long)(rc - n_user) * D;
        }
    }

    // 8 independent 16B loads in flight.
    float4 a[4], b[4];
    #pragma unroll
    for (int j = 0; j < 4; j++) {
        a[j] = __ldg(reinterpret_cast<const float4*>(src[j]) + lane);
        b[j] = __ldg(reinterpret_cast<const float4*>(src[j]) + lane + 8);
    }

    float n0 = sq8(a[0], b[0]);
    float n1 = sq8(a[1], b[1]);
    float n2 = sq8(a[2], b[2]);
    float n3 = sq8(a[3], b[3]);

    #pragma unroll
    for (int o = 4; o > 0; o >>= 1) {
        n0 += __shfl_xor_sync(0xFFFFFFFFu, n0, o);
        n1 += __shfl_xor_sync(0xFFFFFFFFu, n1, o);
        n2 += __shfl_xor_sync(0xFFFFFFFFu, n2, o);
        n3 += __shfl_xor_sync(0xFFFFFFFFu, n3, o);
    }

    if (live[0]) norm_store(a[0], b[0], rsqrtf(n0), dst[0], lane);
    if (live[1]) norm_store(a[1], b[1], rsqrtf(n1), dst[1], lane);
    if (live[2]) norm_store(a[2], b[2], rsqrtf(n2), dst[2], lane);
    if (live[3]) norm_store(a[3], b[3], rsqrtf(n3), dst[3], lane);
}

// ---------------- Phase 2: persistent edge gather + dot (exact R8) --------
__device__ __forceinline__ float dot8h(uint4 w, uint4 z)
{
    const __half2* wh = reinterpret_cast<const __half2*>(&w);
    const __half2* zh = reinterpret_cast<const __half2*>(&z);
    const __half2 p01 = __hfma2(wh[0], zh[0], __hmul2(wh[1], zh[1]));
    const __half2 p23 = __hfma2(wh[2], zh[2], __hmul2(wh[3], zh[3]));
    const float2 f01 = __half22float2(p01);
    const float2 f23 = __half22float2(p23);
    return (f01.x + f01.y) + (f23.x + f23.y);
}

__global__ __launch_bounds__(THREADS, 4) void cosine_gather_kernel(
    const int* __restrict__ src_idx,
    const int* __restrict__ dst_idx,
    float* __restrict__ out,
    int E)
{
    const int gid     = blockIdx.x * THREADS + threadIdx.x;
    const int lane    = gid & 7;
    const int gstride = (GATHER_BLOCKS * THREADS) >> 3;   // quads per sweep
    const int nquads  = E >> 2;                           // full quads

    int g = gid >> 3;
    if (g < nquads) {
        // Prime the pipeline: indices for the first quad.
        int4 s4 = __ldg(reinterpret_cast<const int4*>(src_idx) + g);
        int4 d4 = __ldg(reinterpret_cast<const int4*>(dst_idx) + g);

        while (true) {
            const int gn = g + gstride;

            // Row gathers for the current quad — indices already resident.
            const uint4 w0 = __ldg(reinterpret_cast<const uint4*>(g_nu + (long long)s4.x * D) + lane);
            const uint4 z0 = __ldg(reinterpret_cast<const uint4*>(g_ni + (long long)d4.x * D) + lane);
            const uint4 w1 = __ldg(reinterpret_cast<const uint4*>(g_nu + (long long)s4.y * D) + lane);
            const uint4 z1 = __ldg(reinterpret_cast<const uint4*>(g_ni + (long long)d4.y * D) + lane);
            const uint4 w2 = __ldg(reinterpret_cast<const uint4*>(g_nu + (long long)s4.z * D) + lane);
            const uint4 z2 = __ldg(reinterpret_cast<const uint4*>(g_ni + (long long)d4.z * D) + lane);
            const uint4 w3 = __ldg(reinterpret_cast<const uint4*>(g_nu + (long long)s4.w * D) + lane);
            const uint4 z3 = __ldg(reinterpret_cast<const uint4*>(g_ni + (long long)d4.w * D) + lane);

            // Prefetch next quad's indices while rows are in flight.
            const bool more = gn < nquads;
            if (more) {
                s4 = __ldg(reinterpret_cast<const int4*>(src_idx) + gn);
                d4 = __ldg(reinterpret_cast<const int4*>(dst_idx) + gn);
            }

            float c0 = dot8h(w0, z0);
            float c1 = dot8h(w1, z1);
            float c2 = dot8h(w2, z2);
            float c3 = dot8h(w3, z3);

            #pragma unroll
            for (int o = 4; o > 0; o >>= 1) {
                c0 += __shfl_xor_sync(0xFFFFFFFFu, c0, o);
                c1 += __shfl_xor_sync(0xFFFFFFFFu, c1, o);
                c2 += __shfl_xor_sync(0xFFFFFFFFu, c2, o);
                c3 += __shfl_xor_sync(0xFFFFFFFFu, c3, o);
            }

            if (lane == 0) {
                float4 r; r.x = c0; r.y = c1; r.z = c2; r.w = c3;
                *reinterpret_cast<float4*>(out + g * 4) = r;   // single STG.128
            }

            if (!more) break;
            g = gn;
        }
    }

    // Tail edges (E % 4), handled by the first lane-group of block 0.
    if (blockIdx.x == 0 && (threadIdx.x >> 3) == 0) {
        for (int e = nquads * 4; e < E; e++) {
            const int s = __ldg(src_idx + e);
            const int d = __ldg(dst_idx + e);
            const uint4 w = __ldg(reinterpret_cast<const uint4*>(g_nu + (long long)s * D) + lane);
            const uint4 z = __ldg(reinterpret_cast<const uint4*>(g_ni + (long long)d * D) + lane);
            float c = dot8h(w, z);
            #pragma unroll
            for (int o = 4; o > 0; o >>= 1) c += __shfl_xor_sync(0xFFFFFFFFu, c, o);
            if (lane == 0) out[e] = c;
        }
    }
}

extern "C" void kernel_launch(void* const* d_in, const int* in_sizes, int n_in,
                              void* d_out, int out_size)
{
    const float* h_user = (const float*)d_in[0];
    const float* h_item = (const float*)d_in[1];
    const int*   src    = (const int*)d_in[2];
    const int*   dst    = (const int*)d_in[3];
    float*       out    = (float*)d_out;

    const int N_U = in_sizes[0] / D;
    const int N_I = in_sizes[1] / D;
    const int E   = in_sizes[2];
    const int N_T = N_U + N_I;

    {
        const int rquads = (N_T + 3) / 4;
        const long long t = (long long)rquads * 8;
        normalize_fused_kernel<<<(int)((t + THREADS - 1) / THREADS), THREADS>>>(
            h_user, h_item, N_U, N_T);
    }
    cosine_gather_kernel<<<GATHER_BLOCKS, THREADS>>>(src, dst, out, E);
}